// round 13
// baseline (speedup 1.0000x reference)
#include <cuda_runtime.h>
#include <cuda_bf16.h>

// ROI mean-pool, v13: warp-specialized producer/consumer pipeline with the
// correct named-barrier protocol (bar.arrive = signal, bar.sync = wait).
//   producers (160 thr): fused global-load + split column scan -> double buffer
//   consumers  (96 thr): split row scan + O(1) stitched-corner box phase
//   4 planes per CTA.
//
// fmap: [64,256,80,80] f32   boxes: [64,100,4]   out: [64,100,256]
//
// Buffer M[80][81] (odd stride -> conflict-free everywhere):
//   after col scan: M[r][x] = column prefix (r<40 true, r>=40 local lower half)
//   after row scan: M[r][x] = x-prefix within half (x<40 | x>=40)
// g(y,x): r=y-1, xi=x-1:
//   g = M[r][xi] + (xi>=40 ? M[r][39] : 0)
//     + (y>=41 ? M[39][xi] + (xi>=40 ? M[39][39] : 0) : 0)

#define Bn   64
#define Cn   256
#define Hn   80
#define Wn   80
#define Nn   100
#define SSTR 81
#define KPL  4
#define BUFW (Hn * SSTR)             // 6480 floats per buffer

// ids: FULL0=1 FULL1=2 EMPTY0=3 EMPTY1=4 CONS=5
__device__ __forceinline__ void bar_sync(int id, int cnt) {
    asm volatile("bar.sync %0, %1;" :: "r"(id), "r"(cnt) : "memory");
}
__device__ __forceinline__ void bar_arrive(int id, int cnt) {
    asm volatile("bar.arrive %0, %1;" :: "r"(id), "r"(cnt) : "memory");
}

__device__ __forceinline__ float gfun(const float* __restrict__ M, int y, int x)
{
    if (y == 0 || x == 0) return 0.0f;
    const int r  = y - 1;
    const int xi = x - 1;
    float v = M[r * SSTR + xi];
    if (xi >= 40) v += M[r * SSTR + 39];
    if (y >= 41) {
        v += M[39 * SSTR + xi];
        if (xi >= 40) v += M[39 * SSTR + 39];
    }
    return v;
}

__global__ __launch_bounds__(256, 1)
void roi_pool_v13_kernel(const float* __restrict__ fmap,
                         const float* __restrict__ boxes,
                         float* __restrict__ out)
{
    extern __shared__ __align__(16) float SM[];   // buf0 | buf1 | BC
    int4* BC = reinterpret_cast<int4*>(SM + 2 * BUFW);

    const int p0  = blockIdx.x * KPL;   // 4 consecutive planes, same b
    const int b   = p0 >> 8;
    const int c0  = p0 & 255;
    const int tid = threadIdx.x;

    if (tid < 160) {
        // ---------------- PRODUCER: fused load + column scan --------------
        const int col  = (tid < Wn) ? tid : tid - Wn;
        const int rowb = (tid < Wn) ? 0 : 40;

        #pragma unroll 1
        for (int k = 0; k < KPL; ++k) {
            if (k >= 2) bar_sync(3 + (k & 1), 256);     // wait EMPTY

            const float* __restrict__ g =
                fmap + (size_t)(p0 + k) * (Hn * Wn) + rowb * Wn + col;
            float* __restrict__ d = SM + (k & 1) * BUFW + rowb * SSTR + col;

            float acc = 0.0f;
            #pragma unroll 8
            for (int i = 0; i < 40; ++i) {
                acc += g[i * Wn];        // coalesced; independent of carry
                d[i * SSTR] = acc;       // conflict-free STS
            }
            __threadfence_block();
            bar_arrive(1 + (k & 1), 256);               // signal FULL
        }
    } else {
        // ---------------- CONSUMER: row scan + boxes ----------------------
        const int t = tid - 160;         // 0..95

        // Box coords once (overlaps producers' plane-0 load).
        const float* __restrict__ bx = boxes + (size_t)b * (Nn * 4);
        for (int n = t; n < Nn; n += 96) {
            float4 bb = reinterpret_cast<const float4*>(bx)[n];
            // Match JAX exactly: IEEE div by 640, IEEE mul by 80, trunc, clip.
            int x1 = min(max((int)(__fmul_rn(__fdiv_rn(bb.x, 640.0f), 80.0f)), 0), Wn);
            int y1 = min(max((int)(__fmul_rn(__fdiv_rn(bb.y, 640.0f), 80.0f)), 0), Hn);
            int x2 = min(max((int)(__fmul_rn(__fdiv_rn(bb.z, 640.0f), 80.0f)), 0), Wn);
            int y2 = min(max((int)(__fmul_rn(__fdiv_rn(bb.w, 640.0f), 80.0f)), 0), Hn);
            BC[n] = make_int4(x1, y1, x2, y2);
        }
        bar_sync(5, 96);                 // BC visible to all consumers

        #pragma unroll 1
        for (int k = 0; k < KPL; ++k) {
            bar_sync(1 + (k & 1), 256);  // wait FULL
            float* __restrict__ M = SM + (k & 1) * BUFW;

            // Row scan: 160 tasks (row r, half h); thread t does t and t+96.
            {
                int task = t;
                #pragma unroll
                for (int rep = 0; rep < 2; ++rep, task += 96) {
                    if (task < 160) {
                        const int r = (task < Hn) ? task : task - Hn;
                        const int h = (task < Hn) ? 0 : 1;
                        float* d = M + r * SSTR + 40 * h;
                        float acc = 0.0f;
                        #pragma unroll 8
                        for (int i = 0; i < 40; ++i) {
                            acc += d[i];
                            d[i] = acc;
                        }
                    }
                }
            }
            bar_sync(5, 96);             // row scan done (consumer-local)

            // Box phase: O(1) per box.
            float* __restrict__ ob = out + (size_t)b * (Nn * Cn) + c0 + k;
            for (int n = t; n < Nn; n += 96) {
                int4 q = BC[n];
                float s = gfun(M, q.w, q.z) - gfun(M, q.y, q.z)
                        - gfun(M, q.w, q.x) + gfun(M, q.y, q.x);
                int dy = q.w - q.y;
                int dx = q.z - q.x;
                bool valid = (dy > 0) && (dx > 0);
                int  area  = max(dy * dx, 1);
                ob[(size_t)n * Cn] = valid ? s / (float)area : 0.0f;
            }

            if (k + 2 < KPL) bar_arrive(3 + (k & 1), 256);  // signal EMPTY
        }
    }
}

extern "C" void kernel_launch(void* const* d_in, const int* in_sizes, int n_in,
                              void* d_out, int out_size)
{
    const float* fmap  = (const float*)d_in[0];   // [64,256,80,80]
    const float* boxes = (const float*)d_in[1];   // [64,100,4]
    float*       out   = (float*)d_out;           // [64,100,256]

    (void)in_sizes; (void)n_in; (void)out_size;

    const int smem_bytes = 2 * BUFW * 4 + Nn * 16;        // 53,440 B
    cudaFuncSetAttribute(roi_pool_v13_kernel,
                         cudaFuncAttributeMaxDynamicSharedMemorySize, smem_bytes);

    roi_pool_v13_kernel<<<(Bn * Cn) / KPL, 256, smem_bytes>>>(fmap, boxes, out);
}